// round 2
// baseline (speedup 1.0000x reference)
#include <cuda_runtime.h>
#include <cstdint>

// Problem constants (fixed by the reference: B=8, S=8192, IN=OUT=1024)
#define TOKENS 65536
#define KDIM   1024
#define NDIM   1024

// GEMM tiling
#define BM 128
#define BN 128
#define BK 32
#define PAD 36                  // floats per smem row; stride%32==4 -> conflict-free frag loads
#define NKITER (KDIM / BK)      // 32

// ---------------------------------------------------------------------------
// Device scratch (static globals: allocation-free per the harness rules)
// ---------------------------------------------------------------------------
__device__ int g_cnt[2];            // [0]=visual count, [1]=text count
__device__ int g_mask_is_i32;       // dtype of visual_mask, detected at runtime
__device__ int g_vis[TOKENS];
__device__ int g_txt[TOKENS];

// Detect mask dtype + zero counters.
// int32 {0,1} mask: every 32-bit word <= 1. byte mask (~50% ones): some word
// among the first 64 has a nonzero byte in lanes 1..3 -> value > 1.
// P[byte-mask passes as i32 over 64 words] ~ 2^-192: negligible.
__global__ void init_kernel(const uint32_t* __restrict__ mask32) {
    if (threadIdx.x == 0) {
        int is_i32 = 1;
        #pragma unroll 8
        for (int i = 0; i < 64; i++)
            if (mask32[i] > 1u) { is_i32 = 0; break; }
        g_mask_is_i32 = is_i32;
        g_cnt[0] = 0;
        g_cnt[1] = 0;
    }
}

__global__ void build_lists_kernel(const void* __restrict__ mask) {
    int i = blockIdx.x * blockDim.x + threadIdx.x;
    if (i < TOKENS) {
        int m = g_mask_is_i32 ? ((const int*)mask)[i]
                              : (int)((const unsigned char*)mask)[i];
        if (m) {
            int p = atomicAdd(&g_cnt[0], 1);
            g_vis[p] = i;
        } else {
            int p = atomicAdd(&g_cnt[1], 1);
            g_txt[p] = i;
        }
    }
}

// ---------------------------------------------------------------------------
// Helpers
// ---------------------------------------------------------------------------
__device__ __forceinline__ uint32_t f2tf32(float f) {
    uint32_t u;
    asm("cvt.rna.tf32.f32 %0, %1;" : "=r"(u) : "f"(f));
    return u;
}

__device__ __forceinline__ void cp_async16(uint32_t smem_dst, const void* gmem_src) {
    asm volatile("cp.async.cg.shared.global [%0], [%1], 16;\n"
                 :: "r"(smem_dst), "l"(gmem_src));
}

__device__ __forceinline__ void cp_commit() {
    asm volatile("cp.async.commit_group;\n");
}

// ---------------------------------------------------------------------------
// Routed GEMM: each CTA handles one 128-token tile of ONE route (visual/text)
// and one 128-wide slice of the output dimension.
//   grid.x = NDIM/BN = 8, grid.y = 513 (max tiles: ceil(v/128)+ceil(t/128))
//   256 threads = 8 warps, warp grid 2(m) x 4(n), warp tile 64x32
//   mma.sync.m16n8k8 tf32: per warp 4 m-tiles x 4 n-tiles, fp32 accum
// ---------------------------------------------------------------------------
__global__ void __launch_bounds__(256, 2) routed_gemm_kernel(
    const float* __restrict__ x,
    const float* __restrict__ w_v,
    const float* __restrict__ w_t,
    float* __restrict__ out)
{
    extern __shared__ float smem[];
    float* As = smem;                    // [2][BM][PAD]
    float* Bs = smem + 2 * BM * PAD;     // [2][BN][PAD]
    __shared__ int rows_s[BM];

    const int cv = g_cnt[0];
    const int ct = g_cnt[1];
    const int vis_tiles = (cv + BM - 1) >> 7;

    const int tile = blockIdx.y;
    const int* list;
    const float* W;
    int base, count;
    if (tile < vis_tiles) {
        list = g_vis; W = w_v; base = tile << 7; count = cv;
    } else {
        base = (tile - vis_tiles) << 7;
        count = ct;
        if (base >= count) return;       // tail CTA, nothing to do
        list = g_txt; W = w_t;
    }
    const int mvalid = min(BM, count - base);

    const int tid = threadIdx.x;
    if (tid < BM) rows_s[tid] = (tid < mvalid) ? list[base + tid] : list[base];
    __syncthreads();

    const int n_cta = blockIdx.x * BN;

    // --- async tile loader: A gathered by token row, B from the routed weight
    auto issue_tile = [&](int kt, int buf) {
        const int k0 = kt * BK;
        #pragma unroll
        for (int i = 0; i < 4; i++) {
            int idx = i * 256 + tid;
            int r = idx >> 3, cg = idx & 7;          // 8 x float4 per row
            uint32_t d = (uint32_t)__cvta_generic_to_shared(
                &As[(buf * BM + r) * PAD + cg * 4]);
            cp_async16(d, x + (size_t)rows_s[r] * KDIM + k0 + cg * 4);
        }
        #pragma unroll
        for (int i = 0; i < 4; i++) {
            int idx = i * 256 + tid;
            int r = idx >> 3, cg = idx & 7;
            uint32_t d = (uint32_t)__cvta_generic_to_shared(
                &Bs[(buf * BN + r) * PAD + cg * 4]);
            cp_async16(d, W + (size_t)(n_cta + r) * KDIM + k0 + cg * 4);
        }
        cp_commit();
    };

    const int lane = tid & 31;
    const int g  = lane >> 2;        // 0..7
    const int tg = lane & 3;         // 0..3
    const int wid = tid >> 5;
    const int m0 = (wid >> 2) * 64;  // warp m origin (2 warps in m)
    const int n0 = (wid & 3) * 32;   // warp n origin (4 warps in n)

    float acc[4][4][4];
    #pragma unroll
    for (int mt = 0; mt < 4; mt++)
        #pragma unroll
        for (int nt = 0; nt < 4; nt++)
            #pragma unroll
            for (int r = 0; r < 4; r++) acc[mt][nt][r] = 0.0f;

    issue_tile(0, 0);
    issue_tile(1, 1);

    for (int kt = 0; kt < NKITER; kt++) {
        if (kt + 1 < NKITER) asm volatile("cp.async.wait_group 1;\n");
        else                 asm volatile("cp.async.wait_group 0;\n");
        __syncthreads();

        const int buf = kt & 1;
        const float* Ab = As + buf * BM * PAD;
        const float* Bb = Bs + buf * BN * PAD;

        #pragma unroll
        for (int ks = 0; ks < 4; ks++) {           // 4 k8-steps per BK=32
            const int c = ks * 8 + tg;
            uint32_t a[4][4], b[4][2];
            #pragma unroll
            for (int mt = 0; mt < 4; mt++) {
                const int r = m0 + mt * 16 + g;
                a[mt][0] = f2tf32(Ab[r * PAD + c]);
                a[mt][1] = f2tf32(Ab[(r + 8) * PAD + c]);
                a[mt][2] = f2tf32(Ab[r * PAD + c + 4]);
                a[mt][3] = f2tf32(Ab[(r + 8) * PAD + c + 4]);
            }
            #pragma unroll
            for (int nt = 0; nt < 4; nt++) {
                const int n = n0 + nt * 8 + g;
                b[nt][0] = f2tf32(Bb[n * PAD + c]);
                b[nt][1] = f2tf32(Bb[n * PAD + c + 4]);
            }
            #pragma unroll
            for (int mt = 0; mt < 4; mt++)
                #pragma unroll
                for (int nt = 0; nt < 4; nt++)
                    asm volatile(
                        "mma.sync.aligned.m16n8k8.row.col.f32.tf32.tf32.f32 "
                        "{%0,%1,%2,%3}, {%4,%5,%6,%7}, {%8,%9}, {%0,%1,%2,%3};\n"
                        : "+f"(acc[mt][nt][0]), "+f"(acc[mt][nt][1]),
                          "+f"(acc[mt][nt][2]), "+f"(acc[mt][nt][3])
                        : "r"(a[mt][0]), "r"(a[mt][1]),
                          "r"(a[mt][2]), "r"(a[mt][3]),
                          "r"(b[nt][0]), "r"(b[nt][1]));
        }
        __syncthreads();
        if (kt + 2 < NKITER) issue_tile(kt + 2, buf);
    }

    // --- epilogue: scatter to out[token_row][col], float2 stores
    #pragma unroll
    for (int mt = 0; mt < 4; mt++) {
        const int r_lo = m0 + mt * 16 + g;
        const int r_hi = r_lo + 8;
        #pragma unroll
        for (int nt = 0; nt < 4; nt++) {
            const int col = n_cta + n0 + nt * 8 + tg * 2;
            if (r_lo < mvalid) {
                float2 v = make_float2(acc[mt][nt][0], acc[mt][nt][1]);
                *(float2*)(out + (size_t)rows_s[r_lo] * NDIM + col) = v;
            }
            if (r_hi < mvalid) {
                float2 v = make_float2(acc[mt][nt][2], acc[mt][nt][3]);
                *(float2*)(out + (size_t)rows_s[r_hi] * NDIM + col) = v;
            }
        }
    }
}

// ---------------------------------------------------------------------------
// Launch (graph-capturable: kernels only, no sync, no alloc)
// Inputs (metadata order): x f32[8,8192,1024], visual_mask [8,8192] (dtype
// detected at runtime: int32 or byte), w_v f32[1024,1024], w_t f32[1024,1024]
// ---------------------------------------------------------------------------
extern "C" void kernel_launch(void* const* d_in, const int* in_sizes, int n_in,
                              void* d_out, int out_size)
{
    const float* x    = (const float*)d_in[0];
    const void*  mask = d_in[1];
    const float* w_v  = (const float*)d_in[2];
    const float* w_t  = (const float*)d_in[3];
    float*       out  = (float*)d_out;

    init_kernel<<<1, 32>>>((const uint32_t*)mask);
    build_lists_kernel<<<TOKENS / 256, 256>>>(mask);

    const size_t smem_bytes = (size_t)2 * (BM + BN) * PAD * sizeof(float); // 73728
    cudaFuncSetAttribute(routed_gemm_kernel,
                         cudaFuncAttributeMaxDynamicSharedMemorySize,
                         (int)smem_bytes);

    // max tiles = ceil(v/128)+ceil(t/128) <= 513 for v+t=65536
    dim3 grid(NDIM / BN, 513);
    routed_gemm_kernel<<<grid, 256, smem_bytes>>>(x, w_v, w_t, out);
}